// round 5
// baseline (speedup 1.0000x reference)
#include <cuda_runtime.h>
#include <math.h>

#define MAXN 100000
#define MAXE 1600000
#define MAXEP (MAXN + MAXE)
#define FD 64
#define BN_EPS 1e-5f
#define ATT_SLOPE 0.2f
#define ACT_SLOPE 0.01f

typedef unsigned long long u64;

__device__ __forceinline__ u64 fma2(u64 a, u64 b, u64 c) {
    u64 d;
    asm("fma.rn.f32x2 %0, %1, %2, %3;" : "=l"(d) : "l"(a), "l"(b), "l"(c));
    return d;
}

// ---------------- static device scratch ----------------
__device__ float g_h[(size_t)MAXN * FD];
__device__ float g_agg[(size_t)MAXN * FD];
__device__ float g_ssrc[MAXN];
__device__ float g_sdst[MAXN];
__device__ int   g_deg[MAXN];
__device__ int   g_rowptr[MAXN + 1];
__device__ int   g_cursor[MAXN];
__device__ int   g_csrsrc[MAXEP];
__device__ float g_bnacc[2 * FD];
__device__ int   g_maxbits[4];   // [2*li]=max(0,ssrc), [2*li+1]=max(0,sdst) as int bits

#define SCAN_BS 512
#define NBLK_MAX ((MAXN + SCAN_BS - 1) / SCAN_BS)
__device__ int g_bsum[NBLK_MAX];

// ---------------- CSR build ----------------
__global__ void zero_kernel(int n) {
    int i = blockIdx.x * blockDim.x + threadIdx.x;
    if (i < n) g_deg[i] = 1;              // self-loop pre-counted
    if (i < 2 * FD) g_bnacc[i] = 0.0f;
    if (i < 4) g_maxbits[i] = 0;
}

__global__ void count_kernel(const int* __restrict__ ei, int e) {
    int i = blockIdx.x * blockDim.x + threadIdx.x;
    if (i >= e) return;
    atomicAdd(&g_deg[ei[e + i]], 1);
}

__global__ void scan1_kernel(int n) {
    __shared__ int sh[SCAN_BS];
    int tid = threadIdx.x;
    int idx = blockIdx.x * SCAN_BS + tid;
    int v = (idx < n) ? g_deg[idx] : 0;
    sh[tid] = v;
    __syncthreads();
    for (int off = 1; off < SCAN_BS; off <<= 1) {
        int t = (tid >= off) ? sh[tid - off] : 0;
        __syncthreads();
        sh[tid] += t;
        __syncthreads();
    }
    if (idx < n) g_rowptr[idx] = sh[tid] - v;
    if (tid == SCAN_BS - 1) g_bsum[blockIdx.x] = sh[tid];
}

__global__ void scan2_kernel(int nb, int n) {
    __shared__ int sh[SCAN_BS];
    int tid = threadIdx.x;
    int v = (tid < nb) ? g_bsum[tid] : 0;
    sh[tid] = v;
    __syncthreads();
    for (int off = 1; off < SCAN_BS; off <<= 1) {
        int t = (tid >= off) ? sh[tid - off] : 0;
        __syncthreads();
        sh[tid] += t;
        __syncthreads();
    }
    if (tid < nb) g_bsum[tid] = sh[tid] - v;
    if (tid == nb - 1) g_rowptr[n] = sh[tid];
}

__global__ void scan3_kernel(int n) {
    int i = blockIdx.x * blockDim.x + threadIdx.x;
    if (i >= n) return;
    int r = g_rowptr[i] + g_bsum[i / SCAN_BS];
    g_rowptr[i] = r;
    g_csrsrc[r] = i;        // self-loop occupies slot 0 of each segment
    g_cursor[i] = r + 1;
}

__global__ void fill_kernel(const int* __restrict__ ei, int e) {
    int i = blockIdx.x * blockDim.x + threadIdx.x;
    if (i >= e) return;
    int s = ei[i];
    int d = ei[e + i];
    int p = atomicAdd(&g_cursor[d], 1);
    g_csrsrc[p] = s;
}

// ---------------- GEMM: H = X @ W, f32x2 packed, fused scores + global max ----------------
// 256 threads -> 64 rows x 64 cols. Thread (ty,tx): rows 4ty..+3, cols 4tx..+3.
// xsT[k][row] transposed tile -> LDS.64 yields packed (x_r, x_r+1).
// Wd[k][j] = (w,w) duplicated  -> LDS.128 yields two broadcast pairs.
__global__ void gemm_kernel(const float* __restrict__ X, const float* __restrict__ W,
                            const float* __restrict__ a_src, const float* __restrict__ a_dst,
                            float* __restrict__ H, float* __restrict__ ssrc, float* __restrict__ sdst,
                            int n, int apply_bn,
                            const float* __restrict__ bng, const float* __restrict__ bnb, int li) {
    __shared__ float2 Wd[FD][FD];          // 32 KB duplicated W
    __shared__ float  xsT[FD][FD + 2];     // transposed X tile (+pad, keeps 8B align)
    __shared__ float  as[FD], ad[FD], sc[FD], shf[FD];
    __shared__ float  wmaxS[8], wmaxD[8];

    int tid = threadIdx.x;
    // duplicate W into Wd
    for (int i = tid; i < FD * FD / 4; i += 256) {
        int k = i >> 4;
        int c4 = (i & 15) * 4;
        float4 w = ((const float4*)W)[i];
        Wd[k][c4 + 0] = make_float2(w.x, w.x);
        Wd[k][c4 + 1] = make_float2(w.y, w.y);
        Wd[k][c4 + 2] = make_float2(w.z, w.z);
        Wd[k][c4 + 3] = make_float2(w.w, w.w);
    }
    if (tid < FD) {
        as[tid] = a_src[tid];
        ad[tid] = a_dst[tid];
        if (apply_bn) {
            float invn = 1.0f / (float)n;
            float mean = g_bnacc[tid] * invn;
            float var  = g_bnacc[FD + tid] * invn - mean * mean;
            float istd = rsqrtf(var + BN_EPS);
            float s = istd * bng[tid];
            sc[tid]  = s;
            shf[tid] = bnb[tid] - mean * s;
        }
    }
    __syncthreads();

    int row0 = blockIdx.x * 64;
    // load 64x64 X tile (optional BN+LeakyReLU), store transposed
    for (int i = tid; i < 64 * FD / 4; i += 256) {
        int lr = i >> 4;
        int c4 = (i & 15) * 4;
        int gr = row0 + lr;
        float4 v = make_float4(0.f, 0.f, 0.f, 0.f);
        if (gr < n) v = ((const float4*)X)[(size_t)gr * 16 + (i & 15)];
        if (apply_bn) {
            v.x = v.x * sc[c4]     + shf[c4];
            v.y = v.y * sc[c4 + 1] + shf[c4 + 1];
            v.z = v.z * sc[c4 + 2] + shf[c4 + 2];
            v.w = v.w * sc[c4 + 3] + shf[c4 + 3];
            v.x = (v.x > 0.f) ? v.x : ACT_SLOPE * v.x;
            v.y = (v.y > 0.f) ? v.y : ACT_SLOPE * v.y;
            v.z = (v.z > 0.f) ? v.z : ACT_SLOPE * v.z;
            v.w = (v.w > 0.f) ? v.w : ACT_SLOPE * v.w;
        }
        xsT[c4 + 0][lr] = v.x;
        xsT[c4 + 1][lr] = v.y;
        xsT[c4 + 2][lr] = v.z;
        xsT[c4 + 3][lr] = v.w;
    }
    __syncthreads();

    int ty = tid >> 4, tx = tid & 15;
    int r0 = ty * 4, c0 = tx * 4;

    u64 acc[4][2];   // [col j][row-pair p]: rows (r0+2p, r0+2p+1), col c0+j
#pragma unroll
    for (int j = 0; j < 4; j++) { acc[j][0] = 0ull; acc[j][1] = 0ull; }

#pragma unroll 16
    for (int k = 0; k < FD; k++) {
        u64 x01 = *(const u64*)&xsT[k][r0];
        u64 x23 = *(const u64*)&xsT[k][r0 + 2];
        ulonglong2 wA = *(const ulonglong2*)&Wd[k][c0];       // cols c0, c0+1
        ulonglong2 wB = *(const ulonglong2*)&Wd[k][c0 + 2];   // cols c0+2, c0+3
        acc[0][0] = fma2(x01, wA.x, acc[0][0]);
        acc[0][1] = fma2(x23, wA.x, acc[0][1]);
        acc[1][0] = fma2(x01, wA.y, acc[1][0]);
        acc[1][1] = fma2(x23, wA.y, acc[1][1]);
        acc[2][0] = fma2(x01, wB.x, acc[2][0]);
        acc[2][1] = fma2(x23, wB.x, acc[2][1]);
        acc[3][0] = fma2(x01, wB.y, acc[3][0]);
        acc[3][1] = fma2(x23, wB.y, acc[3][1]);
    }

    // unpack to av[row i][col j]
    float av[4][4];
#pragma unroll
    for (int j = 0; j < 4; j++) {
#pragma unroll
        for (int p = 0; p < 2; p++) {
            float2 f = *(float2*)&acc[j][p];
            av[2 * p][j]     = f.x;
            av[2 * p + 1][j] = f.y;
        }
    }

    float lmS = 0.f, lmD = 0.f;
#pragma unroll
    for (int i = 0; i < 4; i++) {
        int row = row0 + r0 + i;
        if (row < n)
            *(float4*)&H[(size_t)row * FD + c0] =
                make_float4(av[i][0], av[i][1], av[i][2], av[i][3]);
        float ps = av[i][0] * as[c0] + av[i][1] * as[c0 + 1] + av[i][2] * as[c0 + 2] + av[i][3] * as[c0 + 3];
        float pd = av[i][0] * ad[c0] + av[i][1] * ad[c0 + 1] + av[i][2] * ad[c0 + 2] + av[i][3] * ad[c0 + 3];
#pragma unroll
        for (int o = 8; o; o >>= 1) {
            ps += __shfl_down_sync(0xffffffffu, ps, o, 16);
            pd += __shfl_down_sync(0xffffffffu, pd, o, 16);
        }
        if (tx == 0 && row < n) {
            ssrc[row] = ps;
            sdst[row] = pd;
            lmS = fmaxf(lmS, ps);
            lmD = fmaxf(lmD, pd);
        }
    }
#pragma unroll
    for (int o = 16; o; o >>= 1) {
        lmS = fmaxf(lmS, __shfl_xor_sync(0xffffffffu, lmS, o));
        lmD = fmaxf(lmD, __shfl_xor_sync(0xffffffffu, lmD, o));
    }
    int wid = tid >> 5;
    if ((tid & 31) == 0) { wmaxS[wid] = lmS; wmaxD[wid] = lmD; }
    __syncthreads();
    if (tid == 0) {
        float mS = 0.f, mD = 0.f;
#pragma unroll
        for (int w = 0; w < 8; w++) { mS = fmaxf(mS, wmaxS[w]); mD = fmaxf(mD, wmaxD[w]); }
        atomicMax(&g_maxbits[2 * li],     __float_as_int(mS));
        atomicMax(&g_maxbits[2 * li + 1], __float_as_int(mD));
    }
}

// ---------------- Aggregation: warp per dst node, single pass, dual-edge float4 ----------------
__global__ void agg_kernel(const float* __restrict__ H,
                           const float* __restrict__ ssrc, const float* __restrict__ sdst,
                           const float* __restrict__ bias,
                           const float* __restrict__ x0,
                           float* __restrict__ out, int n, int residual, int li) {
    int warp = (blockIdx.x * blockDim.x + threadIdx.x) >> 5;
    int lane = threadIdx.x & 31;
    if (warp >= n) return;
    float M = __int_as_float(g_maxbits[2 * li]) + __int_as_float(g_maxbits[2 * li + 1]);
    int start = g_rowptr[warp];
    int end   = g_rowptr[warp + 1];
    float sd = sdst[warp];
    int half = lane >> 4, sub = lane & 15;

    float z = 0.0f;
    float4 acc = make_float4(0.f, 0.f, 0.f, 0.f);
    const float4* H4 = (const float4*)H;

    for (int base = start; base < end; base += 32) {
        int t = base + lane;
        int s = 0;
        float e = 0.0f;
        if (t < end) {
            s = g_csrsrc[t];
            float lg = ssrc[s] + sd;
            lg = (lg > 0.0f) ? lg : ATT_SLOPE * lg;
            e = __expf(lg - M);
        }
        z += e;
        int cnt = min(32, end - base);
        int cnt2 = (cnt + 1) & ~1;
#pragma unroll 4
        for (int j = 0; j < cnt2; j += 2) {
            int idx = j + half;
            int   sj = __shfl_sync(0xffffffffu, s, idx);
            float ej = __shfl_sync(0xffffffffu, e, idx);
            float4 hv = __ldg(&H4[(size_t)sj * 16 + sub]);
            acc.x += ej * hv.x;
            acc.y += ej * hv.y;
            acc.z += ej * hv.z;
            acc.w += ej * hv.w;
        }
    }
    acc.x += __shfl_xor_sync(0xffffffffu, acc.x, 16);
    acc.y += __shfl_xor_sync(0xffffffffu, acc.y, 16);
    acc.z += __shfl_xor_sync(0xffffffffu, acc.z, 16);
    acc.w += __shfl_xor_sync(0xffffffffu, acc.w, 16);
#pragma unroll
    for (int o = 16; o; o >>= 1) z += __shfl_xor_sync(0xffffffffu, z, o);

    if (half == 0) {
        float inv = 1.0f / z;
        float4 b = ((const float4*)bias)[sub];
        float4 r;
        r.x = acc.x * inv + b.x;
        r.y = acc.y * inv + b.y;
        r.z = acc.z * inv + b.z;
        r.w = acc.w * inv + b.w;
        if (residual) {
            float4 xv = ((const float4*)x0)[(size_t)warp * 16 + sub];
            r.x = 0.5f * (xv.x + r.x);
            r.y = 0.5f * (xv.y + r.y);
            r.z = 0.5f * (xv.z + r.z);
            r.w = 0.5f * (xv.w + r.w);
        }
        ((float4*)out)[(size_t)warp * 16 + sub] = r;
    }
}

// ---------------- BN statistics ----------------
__global__ void bnstats_kernel(const float* __restrict__ A, int n) {
    __shared__ float s1[256], s2[256];
    int tid = threadIdx.x;
    int c = tid & 63;
    int q = tid >> 6;
    float sum = 0.f, sq = 0.f;
    int row0 = blockIdx.x * 64;
    for (int rr = q; rr < 64; rr += 4) {
        int row = row0 + rr;
        if (row < n) {
            float v = A[(size_t)row * FD + c];
            sum += v;
            sq  += v * v;
        }
    }
    s1[tid] = sum; s2[tid] = sq;
    __syncthreads();
    if (q == 0) {
        sum = s1[c] + s1[64 + c] + s1[128 + c] + s1[192 + c];
        sq  = s2[c] + s2[64 + c] + s2[128 + c] + s2[192 + c];
        atomicAdd(&g_bnacc[c], sum);
        atomicAdd(&g_bnacc[FD + c], sq);
    }
}

// ---------------- launch ----------------
extern "C" void kernel_launch(void* const* d_in, const int* in_sizes, int n_in,
                              void* d_out, int out_size) {
    const float* x        = (const float*)d_in[0];
    const float* W1       = (const float*)d_in[1];
    const float* att_src1 = (const float*)d_in[2];
    const float* att_dst1 = (const float*)d_in[3];
    const float* bias1    = (const float*)d_in[4];
    const float* bn_gamma = (const float*)d_in[5];
    const float* bn_beta  = (const float*)d_in[6];
    const float* W2       = (const float*)d_in[7];
    const float* att_src2 = (const float*)d_in[8];
    const float* att_dst2 = (const float*)d_in[9];
    const float* bias2    = (const float*)d_in[10];
    const int*   ei       = (const int*)d_in[11];

    int n = in_sizes[0] / FD;
    int e = in_sizes[11] / 2;

    float* out = (float*)d_out;

    float* d_h    = nullptr;
    float* d_agg  = nullptr;
    float* d_ssrc = nullptr;
    float* d_sdst = nullptr;
    cudaGetSymbolAddress((void**)&d_h, g_h);
    cudaGetSymbolAddress((void**)&d_agg, g_agg);
    cudaGetSymbolAddress((void**)&d_ssrc, g_ssrc);
    cudaGetSymbolAddress((void**)&d_sdst, g_sdst);

    // side stream + events for GEMM1 || CSR-build overlap (host handles only,
    // no device memory; created once, used identically on every call)
    static cudaStream_t s2 = nullptr;
    static cudaEvent_t ev_fork = nullptr, ev_join = nullptr;
    if (!s2) {
        cudaStreamCreateWithFlags(&s2, cudaStreamNonBlocking);
        cudaEventCreateWithFlags(&ev_fork, cudaEventDisableTiming);
        cudaEventCreateWithFlags(&ev_join, cudaEventDisableTiming);
    }

    int nb = (n + SCAN_BS - 1) / SCAN_BS;
    int gemm_grid = (n + 63) / 64;
    int agg_grid  = (n + 7) / 8;

    // --- prologue (zeroes g_maxbits which gemm1 updates) ---
    zero_kernel<<<(n + 255) / 256, 256>>>(n);

    // --- fork: GEMM1 runs concurrently with CSR build ---
    cudaEventRecord(ev_fork, 0);
    cudaStreamWaitEvent(s2, ev_fork, 0);
    gemm_kernel<<<gemm_grid, 256, 0, s2>>>(x, W1, att_src1, att_dst1,
                                           d_h, d_ssrc, d_sdst, n, 0, nullptr, nullptr, 0);
    cudaEventRecord(ev_join, s2);

    // --- CSR build on main stream ---
    count_kernel<<<(e + 255) / 256, 256>>>(ei, e);
    scan1_kernel<<<nb, SCAN_BS>>>(n);
    scan2_kernel<<<1, SCAN_BS>>>(nb, n);
    scan3_kernel<<<(n + 255) / 256, 256>>>(n);
    fill_kernel<<<(e + 255) / 256, 256>>>(ei, e);

    // --- join, then layer-1 aggregation ---
    cudaStreamWaitEvent(0, ev_join, 0);
    agg_kernel<<<agg_grid, 256>>>(d_h, d_ssrc, d_sdst, bias1, nullptr, d_agg, n, 0, 0);

    // --- BN stats ---
    bnstats_kernel<<<(n + 63) / 64, 256>>>(d_agg, n);

    // --- Layer 2 ---
    gemm_kernel<<<gemm_grid, 256>>>(d_agg, W2, att_src2, att_dst2,
                                    d_h, d_ssrc, d_sdst, n, 1, bn_gamma, bn_beta, 1);
    agg_kernel<<<agg_grid, 256>>>(d_h, d_ssrc, d_sdst, bias2, x, out, n, 1, 1);
}

// round 6
// speedup vs baseline: 1.4228x; 1.4228x over previous
#include <cuda_runtime.h>
#include <cuda_fp16.h>
#include <math.h>

#define MAXN 100000
#define MAXE 1600000
#define MAXEP (MAXN + MAXE)
#define FD 64
#define BN_EPS 1e-5f
#define ATT_SLOPE 0.2f
#define ACT_SLOPE 0.01f

// ---------------- static device scratch ----------------
__device__ __half g_h[(size_t)MAXN * FD];    // transformed features in fp16
__device__ float  g_agg[(size_t)MAXN * FD];
__device__ float  g_ssrc[MAXN];
__device__ float  g_sdst[MAXN];
__device__ int    g_deg[MAXN];
__device__ int    g_rowptr[MAXN + 1];
__device__ int    g_cursor[MAXN];
__device__ int    g_csrsrc[MAXEP];
__device__ float  g_bnacc[2 * FD];
__device__ int    g_maxbits[4];   // [2*li]=max(0,ssrc), [2*li+1]=max(0,sdst) as int bits

#define SCAN_BS 512
#define NBLK_MAX ((MAXN + SCAN_BS - 1) / SCAN_BS)
__device__ int g_bsum[NBLK_MAX];

// ---------------- CSR build ----------------
__global__ void zero_kernel(int n) {
    int i = blockIdx.x * blockDim.x + threadIdx.x;
    if (i < n) g_deg[i] = 1;              // self-loop pre-counted
    if (i < 2 * FD) g_bnacc[i] = 0.0f;
    if (i < 4) g_maxbits[i] = 0;
}

__global__ void count_kernel(const int* __restrict__ ei, int e) {
    int i = blockIdx.x * blockDim.x + threadIdx.x;
    if (i >= e) return;
    atomicAdd(&g_deg[ei[e + i]], 1);
}

__global__ void scan1_kernel(int n) {
    __shared__ int sh[SCAN_BS];
    int tid = threadIdx.x;
    int idx = blockIdx.x * SCAN_BS + tid;
    int v = (idx < n) ? g_deg[idx] : 0;
    sh[tid] = v;
    __syncthreads();
    for (int off = 1; off < SCAN_BS; off <<= 1) {
        int t = (tid >= off) ? sh[tid - off] : 0;
        __syncthreads();
        sh[tid] += t;
        __syncthreads();
    }
    if (idx < n) g_rowptr[idx] = sh[tid] - v;
    if (tid == SCAN_BS - 1) g_bsum[blockIdx.x] = sh[tid];
}

__global__ void scan2_kernel(int nb, int n) {
    __shared__ int sh[SCAN_BS];
    int tid = threadIdx.x;
    int v = (tid < nb) ? g_bsum[tid] : 0;
    sh[tid] = v;
    __syncthreads();
    for (int off = 1; off < SCAN_BS; off <<= 1) {
        int t = (tid >= off) ? sh[tid - off] : 0;
        __syncthreads();
        sh[tid] += t;
        __syncthreads();
    }
    if (tid < nb) g_bsum[tid] = sh[tid] - v;
    if (tid == nb - 1) g_rowptr[n] = sh[tid];
}

__global__ void scan3_kernel(int n) {
    int i = blockIdx.x * blockDim.x + threadIdx.x;
    if (i >= n) return;
    int r = g_rowptr[i] + g_bsum[i / SCAN_BS];
    g_rowptr[i] = r;
    g_csrsrc[r] = i;        // self-loop occupies slot 0 of each segment
    g_cursor[i] = r + 1;
}

__global__ void fill_kernel(const int* __restrict__ ei, int e) {
    int i = blockIdx.x * blockDim.x + threadIdx.x;
    if (i >= e) return;
    int s = ei[i];
    int d = ei[e + i];
    int p = atomicAdd(&g_cursor[d], 1);
    g_csrsrc[p] = s;
}

// ---------------- GEMM: H = X @ W (fp32 math, fp16 store), fused scores + global max ----------------
// 256 threads -> 64 rows x 64 cols. Thread (ty=tid>>4, tx=tid&15): rows 4ty..+3, cols 4tx..+3.
__global__ void gemm_kernel(const float* __restrict__ X, const float* __restrict__ W,
                            const float* __restrict__ a_src, const float* __restrict__ a_dst,
                            __half* __restrict__ H, float* __restrict__ ssrc, float* __restrict__ sdst,
                            int n, int apply_bn,
                            const float* __restrict__ bng, const float* __restrict__ bnb, int li) {
    __shared__ float Ws[FD * FD];
    __shared__ float xs[64][FD + 4];
    __shared__ float as[FD], ad[FD], sc[FD], shf[FD];
    __shared__ float wmaxS[8], wmaxD[8];

    int tid = threadIdx.x;
    for (int i = tid; i < FD * FD / 4; i += 256)
        ((float4*)Ws)[i] = ((const float4*)W)[i];
    if (tid < FD) {
        as[tid] = a_src[tid];
        ad[tid] = a_dst[tid];
        if (apply_bn) {
            float invn = 1.0f / (float)n;
            float mean = g_bnacc[tid] * invn;
            float var  = g_bnacc[FD + tid] * invn - mean * mean;
            float istd = rsqrtf(var + BN_EPS);
            float s = istd * bng[tid];
            sc[tid]  = s;
            shf[tid] = bnb[tid] - mean * s;
        }
    }
    __syncthreads();

    int row0 = blockIdx.x * 64;
    for (int i = tid; i < 64 * FD / 4; i += 256) {
        int lr = i >> 4;
        int c4 = (i & 15) * 4;
        int gr = row0 + lr;
        float4 v = make_float4(0.f, 0.f, 0.f, 0.f);
        if (gr < n) v = ((const float4*)X)[(size_t)gr * 16 + (i & 15)];
        if (apply_bn) {
            v.x = v.x * sc[c4]     + shf[c4];
            v.y = v.y * sc[c4 + 1] + shf[c4 + 1];
            v.z = v.z * sc[c4 + 2] + shf[c4 + 2];
            v.w = v.w * sc[c4 + 3] + shf[c4 + 3];
            v.x = (v.x > 0.f) ? v.x : ACT_SLOPE * v.x;
            v.y = (v.y > 0.f) ? v.y : ACT_SLOPE * v.y;
            v.z = (v.z > 0.f) ? v.z : ACT_SLOPE * v.z;
            v.w = (v.w > 0.f) ? v.w : ACT_SLOPE * v.w;
        }
        *(float4*)&xs[lr][c4] = v;
    }
    __syncthreads();

    int ty = tid >> 4, tx = tid & 15;
    int r0 = ty * 4, c0 = tx * 4;
    float acc[4][4];
#pragma unroll
    for (int i = 0; i < 4; i++)
#pragma unroll
        for (int j = 0; j < 4; j++) acc[i][j] = 0.f;

#pragma unroll 16
    for (int k = 0; k < FD; k++) {
        float4 wv = *(const float4*)&Ws[k * FD + c0];
        float x0 = xs[r0][k], x1 = xs[r0 + 1][k], x2 = xs[r0 + 2][k], x3 = xs[r0 + 3][k];
        acc[0][0] += x0 * wv.x; acc[0][1] += x0 * wv.y; acc[0][2] += x0 * wv.z; acc[0][3] += x0 * wv.w;
        acc[1][0] += x1 * wv.x; acc[1][1] += x1 * wv.y; acc[1][2] += x1 * wv.z; acc[1][3] += x1 * wv.w;
        acc[2][0] += x2 * wv.x; acc[2][1] += x2 * wv.y; acc[2][2] += x2 * wv.z; acc[2][3] += x2 * wv.w;
        acc[3][0] += x3 * wv.x; acc[3][1] += x3 * wv.y; acc[3][2] += x3 * wv.z; acc[3][3] += x3 * wv.w;
    }

    float lmS = 0.f, lmD = 0.f;
#pragma unroll
    for (int i = 0; i < 4; i++) {
        int row = row0 + r0 + i;
        if (row < n) {
            // pack 4 fp32 -> 4 fp16 (8 bytes) and store
            __half2 h01 = __floats2half2_rn(acc[i][0], acc[i][1]);
            __half2 h23 = __floats2half2_rn(acc[i][2], acc[i][3]);
            uint2 pk;
            pk.x = *(unsigned*)&h01;
            pk.y = *(unsigned*)&h23;
            ((uint2*)H)[(size_t)row * 16 + tx] = pk;
        }
        float ps = acc[i][0] * as[c0] + acc[i][1] * as[c0 + 1] + acc[i][2] * as[c0 + 2] + acc[i][3] * as[c0 + 3];
        float pd = acc[i][0] * ad[c0] + acc[i][1] * ad[c0 + 1] + acc[i][2] * ad[c0 + 2] + acc[i][3] * ad[c0 + 3];
#pragma unroll
        for (int o = 8; o; o >>= 1) {
            ps += __shfl_down_sync(0xffffffffu, ps, o, 16);
            pd += __shfl_down_sync(0xffffffffu, pd, o, 16);
        }
        if (tx == 0 && row < n) {
            ssrc[row] = ps;
            sdst[row] = pd;
            lmS = fmaxf(lmS, ps);
            lmD = fmaxf(lmD, pd);
        }
    }
#pragma unroll
    for (int o = 16; o; o >>= 1) {
        lmS = fmaxf(lmS, __shfl_xor_sync(0xffffffffu, lmS, o));
        lmD = fmaxf(lmD, __shfl_xor_sync(0xffffffffu, lmD, o));
    }
    int wid = tid >> 5;
    if ((tid & 31) == 0) { wmaxS[wid] = lmS; wmaxD[wid] = lmD; }
    __syncthreads();
    if (tid == 0) {
        float mS = 0.f, mD = 0.f;
#pragma unroll
        for (int w = 0; w < 8; w++) { mS = fmaxf(mS, wmaxS[w]); mD = fmaxf(mD, wmaxD[w]); }
        atomicMax(&g_maxbits[2 * li],     __float_as_int(mS));
        atomicMax(&g_maxbits[2 * li + 1], __float_as_int(mD));
    }
}

// ---------------- Aggregation: warp per dst node, quarter-warp per edge, fp16 gather ----------------
// lane = q*8 + sub (q=0..3 edge slot, sub=0..7 column chunk of 8 halves = 16B)
__global__ void agg_kernel(const __half* __restrict__ H,
                           const float* __restrict__ ssrc, const float* __restrict__ sdst,
                           const float* __restrict__ bias,
                           const float* __restrict__ x0,
                           float* __restrict__ out, int n, int residual, int li) {
    int warp = (blockIdx.x * blockDim.x + threadIdx.x) >> 5;
    int lane = threadIdx.x & 31;
    if (warp >= n) return;
    float M = __int_as_float(g_maxbits[2 * li]) + __int_as_float(g_maxbits[2 * li + 1]);
    int start = g_rowptr[warp];
    int end   = g_rowptr[warp + 1];
    float sd = sdst[warp];
    int q = lane >> 3, sub = lane & 7;

    float z = 0.0f;
    float acc[8];
#pragma unroll
    for (int i = 0; i < 8; i++) acc[i] = 0.f;
    const uint4* H8 = (const uint4*)H;     // 8 x 16B chunks per 128B row

    for (int base = start; base < end; base += 32) {
        int t = base + lane;
        int s = 0;
        float e = 0.0f;
        if (t < end) {
            s = g_csrsrc[t];
            float lg = ssrc[s] + sd;
            lg = (lg > 0.0f) ? lg : ATT_SLOPE * lg;
            e = __expf(lg - M);
        }
        z += e;
        int cnt = min(32, end - base);
#pragma unroll 2
        for (int j = 0; j < cnt; j += 4) {
            int idx = j + q;                       // <= 31 always; idx>=cnt has e==0
            int   sj = __shfl_sync(0xffffffffu, s, idx);
            float ej = __shfl_sync(0xffffffffu, e, idx);
            uint4 hv = __ldg(&H8[(size_t)sj * 8 + sub]);
            float2 f0 = __half22float2(*(__half2*)&hv.x);
            float2 f1 = __half22float2(*(__half2*)&hv.y);
            float2 f2 = __half22float2(*(__half2*)&hv.z);
            float2 f3 = __half22float2(*(__half2*)&hv.w);
            acc[0] += ej * f0.x; acc[1] += ej * f0.y;
            acc[2] += ej * f1.x; acc[3] += ej * f1.y;
            acc[4] += ej * f2.x; acc[5] += ej * f2.y;
            acc[6] += ej * f3.x; acc[7] += ej * f3.y;
        }
    }
    // combine quarters (same sub -> same columns in all 4 quarters)
#pragma unroll
    for (int i = 0; i < 8; i++) {
        acc[i] += __shfl_xor_sync(0xffffffffu, acc[i], 8);
        acc[i] += __shfl_xor_sync(0xffffffffu, acc[i], 16);
    }
#pragma unroll
    for (int o = 16; o; o >>= 1) z += __shfl_xor_sync(0xffffffffu, z, o);

    if (q == 0) {
        float inv = 1.0f / z;
        int c0 = sub * 8;                          // columns c0..c0+7
        float4 b0 = ((const float4*)bias)[sub * 2];
        float4 b1 = ((const float4*)bias)[sub * 2 + 1];
        float4 r0, r1;
        r0.x = acc[0] * inv + b0.x;
        r0.y = acc[1] * inv + b0.y;
        r0.z = acc[2] * inv + b0.z;
        r0.w = acc[3] * inv + b0.w;
        r1.x = acc[4] * inv + b1.x;
        r1.y = acc[5] * inv + b1.y;
        r1.z = acc[6] * inv + b1.z;
        r1.w = acc[7] * inv + b1.w;
        if (residual) {
            float4 xv0 = ((const float4*)x0)[(size_t)warp * 16 + sub * 2];
            float4 xv1 = ((const float4*)x0)[(size_t)warp * 16 + sub * 2 + 1];
            r0.x = 0.5f * (xv0.x + r0.x); r0.y = 0.5f * (xv0.y + r0.y);
            r0.z = 0.5f * (xv0.z + r0.z); r0.w = 0.5f * (xv0.w + r0.w);
            r1.x = 0.5f * (xv1.x + r1.x); r1.y = 0.5f * (xv1.y + r1.y);
            r1.z = 0.5f * (xv1.z + r1.z); r1.w = 0.5f * (xv1.w + r1.w);
        }
        ((float4*)out)[(size_t)warp * 16 + sub * 2]     = r0;
        ((float4*)out)[(size_t)warp * 16 + sub * 2 + 1] = r1;
        (void)c0;
    }
}

// ---------------- BN statistics ----------------
__global__ void bnstats_kernel(const float* __restrict__ A, int n) {
    __shared__ float s1[256], s2[256];
    int tid = threadIdx.x;
    int c = tid & 63;
    int q = tid >> 6;
    float sum = 0.f, sq = 0.f;
    int row0 = blockIdx.x * 64;
    for (int rr = q; rr < 64; rr += 4) {
        int row = row0 + rr;
        if (row < n) {
            float v = A[(size_t)row * FD + c];
            sum += v;
            sq  += v * v;
        }
    }
    s1[tid] = sum; s2[tid] = sq;
    __syncthreads();
    if (q == 0) {
        sum = s1[c] + s1[64 + c] + s1[128 + c] + s1[192 + c];
        sq  = s2[c] + s2[64 + c] + s2[128 + c] + s2[192 + c];
        atomicAdd(&g_bnacc[c], sum);
        atomicAdd(&g_bnacc[FD + c], sq);
    }
}

// ---------------- launch (sequential, single stream) ----------------
extern "C" void kernel_launch(void* const* d_in, const int* in_sizes, int n_in,
                              void* d_out, int out_size) {
    const float* x        = (const float*)d_in[0];
    const float* W1       = (const float*)d_in[1];
    const float* att_src1 = (const float*)d_in[2];
    const float* att_dst1 = (const float*)d_in[3];
    const float* bias1    = (const float*)d_in[4];
    const float* bn_gamma = (const float*)d_in[5];
    const float* bn_beta  = (const float*)d_in[6];
    const float* W2       = (const float*)d_in[7];
    const float* att_src2 = (const float*)d_in[8];
    const float* att_dst2 = (const float*)d_in[9];
    const float* bias2    = (const float*)d_in[10];
    const int*   ei       = (const int*)d_in[11];

    int n = in_sizes[0] / FD;
    int e = in_sizes[11] / 2;

    float* out = (float*)d_out;

    __half* d_h   = nullptr;
    float* d_agg  = nullptr;
    float* d_ssrc = nullptr;
    float* d_sdst = nullptr;
    cudaGetSymbolAddress((void**)&d_h, g_h);
    cudaGetSymbolAddress((void**)&d_agg, g_agg);
    cudaGetSymbolAddress((void**)&d_ssrc, g_ssrc);
    cudaGetSymbolAddress((void**)&d_sdst, g_sdst);

    int nb = (n + SCAN_BS - 1) / SCAN_BS;
    int gemm_grid = (n + 63) / 64;
    int agg_grid  = (n + 7) / 8;

    // --- CSR build ---
    zero_kernel<<<(n + 255) / 256, 256>>>(n);
    count_kernel<<<(e + 255) / 256, 256>>>(ei, e);
    scan1_kernel<<<nb, SCAN_BS>>>(n);
    scan2_kernel<<<1, SCAN_BS>>>(nb, n);
    scan3_kernel<<<(n + 255) / 256, 256>>>(n);
    fill_kernel<<<(e + 255) / 256, 256>>>(ei, e);

    // --- Layer 1 ---
    gemm_kernel<<<gemm_grid, 256>>>(x, W1, att_src1, att_dst1,
                                    d_h, d_ssrc, d_sdst, n, 0, nullptr, nullptr, 0);
    agg_kernel<<<agg_grid, 256>>>(d_h, d_ssrc, d_sdst, bias1, nullptr, d_agg, n, 0, 0);

    // --- BN stats ---
    bnstats_kernel<<<(n + 63) / 64, 256>>>(d_agg, n);

    // --- Layer 2 ---
    gemm_kernel<<<gemm_grid, 256>>>(d_agg, W2, att_src2, att_dst2,
                                    d_h, d_ssrc, d_sdst, n, 1, bn_gamma, bn_beta, 1);
    agg_kernel<<<agg_grid, 256>>>(d_h, d_ssrc, d_sdst, bias2, x, out, n, 1, 1);
}